// round 1
// baseline (speedup 1.0000x reference)
#include <cuda_runtime.h>
#include <cstdint>
#include <math.h>

// Symmetric Hausdorff distance.
// prediction:   [B, N, 3] fp32
// ground_truth: [B, M, 3] fp32
// out:          [B] fp32
//
// Strategy: s(n,m) = 0.5|x|^2 + 0.5|y|^2 - x.y  (= 0.5 d^2, symmetric).
// One pass over all pairs updates BOTH row-mins (min over m, per n) and
// col-mins (min over n, per m). Mins kept as int bit patterns (all values
// clamped >= 0, so int ordering == float ordering) so atomicMin is exact
// and deterministic. Finalize: out[b] = sqrt(2 * max(all mins of batch b)).

#define BATCH 4
#define NPTS 8192
#define MPTS 8192
#define TN 8              // n-points per thread (register tile)
#define BLOCK 128
#define NCHUNK (BLOCK*TN) // 1024 n per block
#define MCHUNK 1024       // m per block (shared tile)

#define FINF_BITS 0x7f800000

__device__ int g_rowmin[BATCH * NPTS];
__device__ int g_colmin[BATCH * MPTS];

__global__ void hd_init() {
    int i = blockIdx.x * blockDim.x + threadIdx.x;
    if (i < BATCH * NPTS) g_rowmin[i] = FINF_BITS;
    if (i < BATCH * MPTS) g_colmin[i] = FINF_BITS;
}

__global__ __launch_bounds__(BLOCK) void hd_main(const float* __restrict__ pred,
                                                 const float* __restrict__ gt) {
    __shared__ float4 sy[MCHUNK];

    const int b     = blockIdx.z;
    const int nbase = blockIdx.x * NCHUNK;
    const int mbase = blockIdx.y * MCHUNK;
    const int tid   = threadIdx.x;

    // Stage this block's m-tile: {-y0, -y1, -y2, 0.5*|y|^2} per point.
    for (int k = tid; k < MCHUNK; k += BLOCK) {
        const float* g = gt + ((size_t)(b * MPTS + mbase + k)) * 3;
        float y0 = g[0], y1 = g[1], y2 = g[2];
        sy[k] = make_float4(-y0, -y1, -y2, 0.5f * (y0*y0 + y1*y1 + y2*y2));
    }

    // Register tile of TN n-points for this thread.
    float x0[TN], x1[TN], x2[TN], cn[TN], rmin[TN];
#pragma unroll
    for (int i = 0; i < TN; i++) {
        const float* p = pred + ((size_t)(b * NPTS + nbase + tid * TN + i)) * 3;
        x0[i] = p[0]; x1[i] = p[1]; x2[i] = p[2];
        cn[i] = 0.5f * (x0[i]*x0[i] + x1[i]*x1[i] + x2[i]*x2[i]);
        rmin[i] = __int_as_float(FINF_BITS);
    }
    __syncthreads();

    int* colm = g_colmin + b * MPTS + mbase;

#pragma unroll 2
    for (int j = 0; j < MCHUNK; j++) {
        const float4 y = sy[j];           // one LDS.128, conflict-free
        float colv = __int_as_float(FINF_BITS);
#pragma unroll
        for (int i = 0; i < TN; i++) {
            float t = cn[i] + y.w;        // 0.5|x|^2 + 0.5|y|^2
            t = fmaf(x0[i], y.x, t);      // - x.y  (y stored negated)
            t = fmaf(x1[i], y.y, t);
            t = fmaf(x2[i], y.z, t);
            rmin[i] = fminf(rmin[i], t);
            colv    = fminf(colv, t);
        }
        // Fire-and-forget reduction (REDG); min over this thread's TN n's.
        atomicMin(&colm[j], __float_as_int(fmaxf(colv, 0.0f)));
    }

    int* rowm = g_rowmin + b * NPTS + nbase + tid * TN;
#pragma unroll
    for (int i = 0; i < TN; i++)
        atomicMin(&rowm[i], __float_as_int(fmaxf(rmin[i], 0.0f)));
}

__global__ void hd_finalize(float* __restrict__ out) {
    __shared__ float red[256];
    const int b = blockIdx.x;
    const int tid = threadIdx.x;
    float v = 0.0f;   // all mins are >= 0
    for (int i = tid; i < NPTS; i += 256)
        v = fmaxf(v, __int_as_float(g_rowmin[b * NPTS + i]));
    for (int i = tid; i < MPTS; i += 256)
        v = fmaxf(v, __int_as_float(g_colmin[b * MPTS + i]));
    red[tid] = v;
    __syncthreads();
    for (int s = 128; s > 0; s >>= 1) {
        if (tid < s) red[tid] = fmaxf(red[tid], red[tid + s]);
        __syncthreads();
    }
    if (tid == 0) out[b] = sqrtf(fmaxf(2.0f * red[0], 0.0f));
}

extern "C" void kernel_launch(void* const* d_in, const int* in_sizes, int n_in,
                              void* d_out, int out_size) {
    const float* pred = (const float*)d_in[0];
    const float* gt   = (const float*)d_in[1];
    float* out = (float*)d_out;

    hd_init<<<(BATCH * NPTS + 255) / 256, 256>>>();

    dim3 grid(NPTS / NCHUNK, MPTS / MCHUNK, BATCH);   // (8, 8, 4) = 256 blocks
    hd_main<<<grid, BLOCK>>>(pred, gt);

    hd_finalize<<<BATCH, 256>>>(out);
}

// round 2
// speedup vs baseline: 1.0212x; 1.0212x over previous
#include <cuda_runtime.h>
#include <cstdint>
#include <math.h>

// Symmetric Hausdorff distance, B=4, N=M=8192, D=3, fp32.
//
// s(n,m) = 0.5|x|^2 + 0.5|y|^2 - x.y  (= 0.5 d^2, symmetric, >= 0 up to rounding).
// One pass updates BOTH row-mins (min over m per n, in registers) and col-mins
// (min over n per m, via warp REDUX + single-lane global atomicMin on int bit
// patterns -- exact & order-independent for clamped nonnegative floats).
// Finalize: out[b] = sqrt(2 * max(all mins)).
//
// Inner product packed as fma.rn.f32x2 (FFMA2): 2 fma-pipe ops per pair.

#define BATCH 4
#define NPTS 8192
#define MPTS 8192
#define TN 16                 // n-points per thread (8 f32x2 pairs)
#define BLOCK 128
#define NCHUNK (BLOCK*TN)     // 2048 n per block
#define MCHUNK 512            // m per block (shared tile)

#define FINF_BITS 0x7f800000

typedef unsigned long long ull;

__device__ int g_rowmin[BATCH * NPTS];
__device__ int g_colmin[BATCH * MPTS];

__device__ __forceinline__ ull pack2(float a, float b) {
    ull r; asm("mov.b64 %0, {%1, %2};" : "=l"(r) : "f"(a), "f"(b)); return r;
}
__device__ __forceinline__ float2 unpack2(ull v) {
    float2 f; asm("mov.b64 {%0, %1}, %2;" : "=f"(f.x), "=f"(f.y) : "l"(v)); return f;
}
__device__ __forceinline__ ull add2(ull a, ull b) {
    ull r; asm("add.rn.f32x2 %0, %1, %2;" : "=l"(r) : "l"(a), "l"(b)); return r;
}
__device__ __forceinline__ ull fma2(ull a, ull b, ull c) {
    ull r; asm("fma.rn.f32x2 %0, %1, %2, %3;" : "=l"(r) : "l"(a), "l"(b), "l"(c)); return r;
}

__global__ void hd_init() {
    int i = blockIdx.x * blockDim.x + threadIdx.x;
    if (i < BATCH * NPTS) g_rowmin[i] = FINF_BITS;
    if (i < BATCH * MPTS) g_colmin[i] = FINF_BITS;
}

__global__ __launch_bounds__(BLOCK) void hd_main(const float* __restrict__ pred,
                                                 const float* __restrict__ gt) {
    // Per m-point: { {-y0,-y0}, {-y1,-y1} } and { {-y2,-y2}, {w,w} } pre-packed.
    __shared__ ulonglong2 sy[MCHUNK * 2];

    const int b     = blockIdx.z;
    const int nbase = blockIdx.x * NCHUNK;
    const int mbase = blockIdx.y * MCHUNK;
    const int tid   = threadIdx.x;
    const int lane  = tid & 31;

    for (int k = tid; k < MCHUNK; k += BLOCK) {
        const float* g = gt + ((size_t)(b * MPTS + mbase + k)) * 3;
        float y0 = g[0], y1 = g[1], y2 = g[2];
        float w  = 0.5f * (y0*y0 + y1*y1 + y2*y2);
        sy[2*k]     = make_ulonglong2(pack2(-y0, -y0), pack2(-y1, -y1));
        sy[2*k + 1] = make_ulonglong2(pack2(-y2, -y2), pack2(w, w));
    }

    // Register tile: TN n-points as TN/2 f32x2 pairs.
    ull X0[TN/2], X1[TN/2], X2[TN/2], CN[TN/2];
    float rmin[TN];
#pragma unroll
    for (int p = 0; p < TN/2; p++) {
        const float* pa = pred + ((size_t)(b * NPTS + nbase + tid * TN + 2*p)) * 3;
        float a0 = pa[0], a1 = pa[1], a2 = pa[2];
        float b0 = pa[3], b1 = pa[4], b2 = pa[5];
        X0[p] = pack2(a0, b0);
        X1[p] = pack2(a1, b1);
        X2[p] = pack2(a2, b2);
        CN[p] = pack2(0.5f * (a0*a0 + a1*a1 + a2*a2),
                      0.5f * (b0*b0 + b1*b1 + b2*b2));
        rmin[2*p]   = __int_as_float(FINF_BITS);
        rmin[2*p+1] = __int_as_float(FINF_BITS);
    }
    __syncthreads();

    int* colm = g_colmin + b * MPTS + mbase;

#pragma unroll 1
    for (int j = 0; j < MCHUNK; j++) {
        const ulonglong2 ya = sy[2*j];       // LDS.128 broadcast (N=1, cheap)
        const ulonglong2 yb = sy[2*j + 1];
        float c0 = __int_as_float(FINF_BITS);
        float c1 = __int_as_float(FINF_BITS);
#pragma unroll
        for (int p = 0; p < TN/2; p++) {
            ull t = add2(CN[p], yb.y);       // 0.5|x|^2 + 0.5|y|^2 (both lanes)
            t = fma2(X0[p], ya.x, t);        // - x.y (y negated)
            t = fma2(X1[p], ya.y, t);
            t = fma2(X2[p], yb.x, t);
            float2 f = unpack2(t);
            rmin[2*p]   = fminf(rmin[2*p],   f.x);
            rmin[2*p+1] = fminf(rmin[2*p+1], f.y);
            c0 = fminf(c0, f.x);
            c1 = fminf(c1, f.y);
        }
        // Warp-exact min: clamp >=0 so int bit ordering == float ordering.
        unsigned cv = (unsigned)__float_as_int(fmaxf(fminf(c0, c1), 0.0f));
        unsigned wm = __reduce_min_sync(0xffffffffu, cv);
        if (lane == 0) atomicMin(&colm[j], (int)wm);
    }

    int* rowm = g_rowmin + b * NPTS + nbase + tid * TN;
#pragma unroll
    for (int i = 0; i < TN; i++)
        atomicMin(&rowm[i], __float_as_int(fmaxf(rmin[i], 0.0f)));
}

__global__ void hd_finalize(float* __restrict__ out) {
    __shared__ float red[256];
    const int b = blockIdx.x;
    const int tid = threadIdx.x;
    float v = 0.0f;   // all mins are >= 0
    for (int i = tid; i < NPTS; i += 256)
        v = fmaxf(v, __int_as_float(g_rowmin[b * NPTS + i]));
    for (int i = tid; i < MPTS; i += 256)
        v = fmaxf(v, __int_as_float(g_colmin[b * MPTS + i]));
    red[tid] = v;
    __syncthreads();
    for (int s = 128; s > 0; s >>= 1) {
        if (tid < s) red[tid] = fmaxf(red[tid], red[tid + s]);
        __syncthreads();
    }
    if (tid == 0) out[b] = sqrtf(fmaxf(2.0f * red[0], 0.0f));
}

extern "C" void kernel_launch(void* const* d_in, const int* in_sizes, int n_in,
                              void* d_out, int out_size) {
    const float* pred = (const float*)d_in[0];
    const float* gt   = (const float*)d_in[1];
    float* out = (float*)d_out;

    hd_init<<<(BATCH * NPTS + 255) / 256, 256>>>();

    dim3 grid(NPTS / NCHUNK, MPTS / MCHUNK, BATCH);   // (4, 16, 4) = 256 blocks
    hd_main<<<grid, BLOCK>>>(pred, gt);

    hd_finalize<<<BATCH, 256>>>(out);
}